// round 4
// baseline (speedup 1.0000x reference)
#include <cuda_runtime.h>
#include <cuda_bf16.h>

// Problem constants (fixed by the dataset)
#define BB   64
#define MM   64   // ctrl rows (u direction)
#define NN   64   // ctrl cols (v direction)
#define OUT  512  // output grid per dim
#define PP   3    // degree -> 4 basis funcs

#define U_TILE 128
#define V_TILE 128
#define THREADS 128

// out[b,u,v,:] = (sum_{l,r} Nu[u,l]*Nv[v,r]*ctrl[b, iu0(u)+l, iv0(v)+r, 0..3]) -> xyz/w
__global__ __launch_bounds__(THREADS) void surfeval_kernel(
    const float4* __restrict__ ctrl4,   // (B, M, N) float4 (xyzw)
    const float4* __restrict__ Nu4,     // (OUT) float4
    const float4* __restrict__ Nv4,     // (OUT) float4
    const int* __restrict__ iu,         // (OUT,4) int32  (JAX downcasts int64->int32)
    const int* __restrict__ iv,         // (OUT,4) int32
    float* __restrict__ out)            // (B, OUT, OUT, 3)
{
    __shared__ float4 s_Nu[U_TILE];
    __shared__ int    s_row0[U_TILE];

    const int tid  = threadIdx.x;
    const int vt   = blockIdx.x;          // v tile
    const int ut   = blockIdx.y;          // u tile
    const int b    = blockIdx.z;

    const int u_lo = ut * U_TILE;
    const int u_hi = u_lo + U_TILE;

    // cooperative load of Nu + row0 for this u tile
    s_Nu[tid]   = __ldg(&Nu4[u_lo + tid]);
    s_row0[tid] = __ldg(&iu[(u_lo + tid) * 4]);
    __syncthreads();

    const int v = vt * V_TILE + tid;
    const float4 nv = __ldg(&Nv4[v]);
    const int iv0 = __ldg(&iv[v * 4]);

    // base pointer for this batch, shifted to column iv0
    const float4* cb = ctrl4 + ((size_t)b * MM * NN) + iv0;

    int u = u_lo;
    #pragma unroll 1
    while (u < u_hi) {
        const int row0 = s_row0[u - u_lo];

        // rowdot[l] = sum_r Nv[v,r] * ctrl[b, row0+l, iv0+r, :]
        float4 rd0, rd1, rd2, rd3;
        {
            const float4* p = cb + (size_t)row0 * NN;
            float4 c0 = p[0], c1 = p[1], c2 = p[2], c3 = p[3];
            rd0.x = nv.x*c0.x + nv.y*c1.x + nv.z*c2.x + nv.w*c3.x;
            rd0.y = nv.x*c0.y + nv.y*c1.y + nv.z*c2.y + nv.w*c3.y;
            rd0.z = nv.x*c0.z + nv.y*c1.z + nv.z*c2.z + nv.w*c3.z;
            rd0.w = nv.x*c0.w + nv.y*c1.w + nv.z*c2.w + nv.w*c3.w;
            p += NN;
            c0 = p[0]; c1 = p[1]; c2 = p[2]; c3 = p[3];
            rd1.x = nv.x*c0.x + nv.y*c1.x + nv.z*c2.x + nv.w*c3.x;
            rd1.y = nv.x*c0.y + nv.y*c1.y + nv.z*c2.y + nv.w*c3.y;
            rd1.z = nv.x*c0.z + nv.y*c1.z + nv.z*c2.z + nv.w*c3.z;
            rd1.w = nv.x*c0.w + nv.y*c1.w + nv.z*c2.w + nv.w*c3.w;
            p += NN;
            c0 = p[0]; c1 = p[1]; c2 = p[2]; c3 = p[3];
            rd2.x = nv.x*c0.x + nv.y*c1.x + nv.z*c2.x + nv.w*c3.x;
            rd2.y = nv.x*c0.y + nv.y*c1.y + nv.z*c2.y + nv.w*c3.y;
            rd2.z = nv.x*c0.z + nv.y*c1.z + nv.z*c2.z + nv.w*c3.z;
            rd2.w = nv.x*c0.w + nv.y*c1.w + nv.z*c2.w + nv.w*c3.w;
            p += NN;
            c0 = p[0]; c1 = p[1]; c2 = p[2]; c3 = p[3];
            rd3.x = nv.x*c0.x + nv.y*c1.x + nv.z*c2.x + nv.w*c3.x;
            rd3.y = nv.x*c0.y + nv.y*c1.y + nv.z*c2.y + nv.w*c3.y;
            rd3.z = nv.x*c0.z + nv.y*c1.z + nv.z*c2.z + nv.w*c3.z;
            rd3.w = nv.x*c0.w + nv.y*c1.w + nv.z*c2.w + nv.w*c3.w;
        }

        // sweep all u sharing this span (same row0)
        #pragma unroll 1
        do {
            const float4 nu = s_Nu[u - u_lo];
            float4 acc;
            acc.x = nu.x*rd0.x + nu.y*rd1.x + nu.z*rd2.x + nu.w*rd3.x;
            acc.y = nu.x*rd0.y + nu.y*rd1.y + nu.z*rd2.y + nu.w*rd3.y;
            acc.z = nu.x*rd0.z + nu.y*rd1.z + nu.z*rd2.z + nu.w*rd3.z;
            acc.w = nu.x*rd0.w + nu.y*rd1.w + nu.z*rd2.w + nu.w*rd3.w;

            const float inv = __fdividef(1.0f, acc.w);
            const size_t o = (((size_t)b * OUT + u) * OUT + v) * 3;
            out[o + 0] = acc.x * inv;
            out[o + 1] = acc.y * inv;
            out[o + 2] = acc.z * inv;
            ++u;
        } while (u < u_hi && s_row0[u - u_lo] == row0);
    }
}

extern "C" void kernel_launch(void* const* d_in, const int* in_sizes, int n_in,
                              void* d_out, int out_size) {
    const float4* ctrl = (const float4*)d_in[0];
    const float4* Nu   = (const float4*)d_in[1];
    const float4* Nv   = (const float4*)d_in[2];
    const int*    iu   = (const int*)d_in[3];
    const int*    iv   = (const int*)d_in[4];
    float*        out  = (float*)d_out;

    dim3 grid(OUT / V_TILE, OUT / U_TILE, BB);   // (4, 4, 64)
    surfeval_kernel<<<grid, THREADS>>>(ctrl, Nu, Nv, iu, iv, out);
}